// round 3
// baseline (speedup 1.0000x reference)
#include <cuda_runtime.h>
#include <stdint.h>

// MinusSpan: B=16, T=2048, D=1024 (H=512), N_SPANS=256
// out[b,s] = concat(fwd[j]-f_pre, bwd[i]-b_post, f_pre, b_post), zeroed if i==0&&j==0
// f_pre = fwd[i-1] if i>=1 else 0 ; b_post = bwd[j+1] if j+1<T else 0

static constexpr int Bc = 16;
static constexpr int Tc = 2048;
static constexpr int Dc = 1024;
static constexpr int Hc = Dc / 2;           // 512
static constexpr int NS = 256;
static constexpr int D4 = Dc / 4;           // 256 float4 per (b,t) row
static constexpr int H4 = Hc / 4;           // 128 float4 per half-row
static constexpr int NSPAN_TOT = Bc * NS;   // 4096 spans

// Flag: 1 if span_idxs buffer is int64, 0 if int32. Set by detect_kernel.
__device__ int g_idx_is64;

// Detect index dtype by scanning the first 2*NSPAN_TOT 32-bit words
// (safe under both interpretations: int32 buffer has exactly 2*NSPAN_TOT
// words; int64 buffer has 4*NSPAN_TOT). If the data is int64 (values in
// [0,2048), little-endian), every odd word is a zero high-half. If int32,
// odd words are j-values, which are nonzero w.p. 2047/2048 each — the
// probability ALL 4096 sampled odd words are zero is ~0.
__global__ void detect_idx_dtype_kernel(const unsigned int* __restrict__ w)
{
    __shared__ int any_nonzero;
    if (threadIdx.x == 0) any_nonzero = 0;
    __syncthreads();
    int local = 0;
    for (int k = threadIdx.x; k < NSPAN_TOT; k += blockDim.x) {
        // odd word index: 2k+1
        if (w[2 * k + 1] != 0u) local = 1;
    }
    if (local) atomicOr(&any_nonzero, 1);
    __syncthreads();
    if (threadIdx.x == 0) g_idx_is64 = (any_nonzero == 0) ? 1 : 0;
}

__global__ __launch_bounds__(128, 8)
void minus_span_kernel(const float* __restrict__ inp,
                       const int* __restrict__ idx32,   // same buffer, two views
                       const long long* __restrict__ idx64,
                       float* __restrict__ out)
{
    const int span = blockIdx.x;            // 0 .. NSPAN_TOT-1
    const int b    = span >> 8;             // span / NS
    const int t    = threadIdx.x;           // 0..127 (one float4 per region)

    long long i, j;
    if (g_idx_is64) {
        i = idx64[(size_t)span * 2 + 0];
        j = idx64[(size_t)span * 2 + 1];
    } else {
        i = idx32[(size_t)span * 2 + 0];
        j = idx32[(size_t)span * 2 + 1];
    }

    const bool skip     = (i == 0) && (j == 0);
    const bool has_pre  = !skip && (i >= 1);
    const bool has_post = !skip && (j + 1 < Tc);

    // Safety clamp: never fault even if indices are garbage.
    long long ic = i < 0 ? 0 : (i >= Tc ? Tc - 1 : i);
    long long jc = j < 0 ? 0 : (j >= Tc ? Tc - 1 : j);
    long long ip = ic >= 1 ? ic - 1 : 0;            // i-1 clamped
    long long jn = (jc + 1 < Tc) ? jc + 1 : Tc - 1; // j+1 clamped

    const float4* __restrict__ base =
        reinterpret_cast<const float4*>(inp) + (size_t)b * Tc * D4;
    float4* __restrict__ o =
        reinterpret_cast<float4*>(out) + (size_t)span * (4 * H4);

    const float4 zero = make_float4(0.f, 0.f, 0.f, 0.f);

    // Batch all gathers up front (independent LDG.128s -> high MLP)
    float4 f_end   = zero, b_start = zero, f_pre = zero, b_post = zero;
    if (!skip) {
        f_end   = base[(size_t)jc * D4 + t];            // fwd[j]
        b_start = base[(size_t)ic * D4 + H4 + t];       // bwd[i]
    }
    if (has_pre)  f_pre  = base[(size_t)ip * D4 + t];       // fwd[i-1]
    if (has_post) b_post = base[(size_t)jn * D4 + H4 + t];  // bwd[j+1]

    float4 r0 = make_float4(f_end.x - f_pre.x,  f_end.y - f_pre.y,
                            f_end.z - f_pre.z,  f_end.w - f_pre.w);
    float4 r1 = make_float4(b_start.x - b_post.x, b_start.y - b_post.y,
                            b_start.z - b_post.z, b_start.w - b_post.w);

    o[t]          = r0;      // f_end - f_pre
    o[H4 + t]     = r1;      // b_start - b_post
    o[2 * H4 + t] = f_pre;   // f_pre (zero when invalid/skip)
    o[3 * H4 + t] = b_post;  // b_post
}

extern "C" void kernel_launch(void* const* d_in, const int* in_sizes, int n_in,
                              void* d_out, int out_size)
{
    // Select inputs by element count, immune to ordering:
    // input: B*T*D = 33,554,432 elements; span_idxs: B*N_SPANS*2 = 8,192.
    int big = (in_sizes[0] >= in_sizes[1]) ? 0 : 1;
    int small = 1 - big;

    const float* inp  = (const float*)d_in[big];
    const void*  idxs = d_in[small];
    float*       out  = (float*)d_out;

    detect_idx_dtype_kernel<<<1, 256>>>((const unsigned int*)idxs);
    minus_span_kernel<<<NSPAN_TOT, 128>>>(
        inp, (const int*)idxs, (const long long*)idxs, out);
}